// round 4
// baseline (speedup 1.0000x reference)
#include <cuda_runtime.h>
#include <cstdint>

#define CCH 64
#define CO 8
#define WIN 13
#define WPB 8
#define TP 104
#define PADW 20          // xs per-window pitch (floats)
#define XROW 160         // WPB*PADW
#define WVP 66           // wvT pitch (2-way store conflict only, 8B-aligned rows)
#define QKP 12           // qT/kT row pitch (48B -> conflict-floor LDS.128)
#define ARP 20           // att row pitch (floats)
#define AWS 260          // att window stride = 13*ARP
#define NTHREADS 256
#define NVOX 53248
#define TILES_PER_B 512

// byte offsets into dynamic smem
#define OFF_XS   0            // 64*160*4      = 40960
#define OFF_WVT  40960        // 64*66*4       = 16896
#define OFF_ATT  57856        // 8*260*4       = 8320 (aliases wq/wk, dead by then)
#define OFF_WQ   57856        // 64*8*4        = 2048
#define OFF_WK   59904        // 2048
#define OFF_QT   66176        // 104*12*4      = 4992
#define OFF_KT   71168        // 4992
#define OFF_BQ   76160        // 32
#define OFF_BK   76192        // 32
#define OFF_BV   76224        // 256
#define SMEM_BYTES 76480

typedef unsigned long long u64;

__device__ __forceinline__ u64 fma2(u64 a, u64 b, u64 c) {
    u64 d;
    asm("fma.rn.f32x2 %0, %1, %2, %3;" : "=l"(d) : "l"(a), "l"(b), "l"(c));
    return d;
}
__device__ __forceinline__ u64 mul2(u64 a, u64 b) {
    u64 d;
    asm("mul.rn.f32x2 %0, %1, %2;" : "=l"(d) : "l"(a), "l"(b));
    return d;
}
__device__ __forceinline__ u64 dup2(float x) {
    u64 d; unsigned xi = __float_as_uint(x);
    asm("mov.b64 %0, {%1, %1};" : "=l"(d) : "r"(xi));
    return d;
}
__device__ __forceinline__ float lo2(u64 v) { return __uint_as_float((unsigned)v); }
__device__ __forceinline__ float hi2(u64 v) { return __uint_as_float((unsigned)(v >> 32)); }

__global__ __launch_bounds__(NTHREADS, 3)
void win_attn_kernel(const float* __restrict__ x,
                     const float* __restrict__ wq, const float* __restrict__ bq,
                     const float* __restrict__ wk, const float* __restrict__ bk,
                     const float* __restrict__ wv, const float* __restrict__ bv,
                     float* __restrict__ out) {
    extern __shared__ char smem[];
    float* s_xs  = (float*)(smem + OFF_XS);
    float* s_wvT = (float*)(smem + OFF_WVT);
    float* s_att = (float*)(smem + OFF_ATT);
    float* s_wq  = (float*)(smem + OFF_WQ);
    float* s_wk  = (float*)(smem + OFF_WK);
    float* s_qT  = (float*)(smem + OFF_QT);
    float* s_kT  = (float*)(smem + OFF_KT);
    float* s_bq  = (float*)(smem + OFF_BQ);
    float* s_bk  = (float*)(smem + OFF_BK);
    float* s_bv  = (float*)(smem + OFF_BV);

    const int tid  = threadIdx.x;
    const int b    = blockIdx.x / TILES_PER_B;
    const int tile = blockIdx.x % TILES_PER_B;
    const long n0  = (long)tile * TP;

    const float* xb = x   + (long)b * CCH * NVOX + n0;
    float*       ob = out + (long)b * CCH * NVOX + n0;

    // ---- weights (transposed) + biases into shared ----
    for (int i = tid; i < CO * CCH; i += NTHREADS) {
        int o = i / CCH, c = i % CCH;
        s_wq[c * CO + o] = wq[i];
        s_wk[c * CO + o] = wk[i];
    }
    for (int i = tid; i < CCH * CCH; i += NTHREADS) {
        int c = i / CCH, cc = i % CCH;
        s_wvT[cc * WVP + c] = wv[i];
    }
    if (tid < CO)                      s_bq[tid]       = bq[tid];
    if (tid >= 64 && tid < 64 + CO)    s_bk[tid - 64]  = bk[tid - 64];
    if (tid >= 128 && tid < 128 + CCH) s_bv[tid - 128] = bv[tid - 128];

    // ---- x tile -> window-padded smem ----
    for (int i = tid; i < CCH * (TP / 4); i += NTHREADS) {
        int r  = i / (TP / 4);
        int c4 = i % (TP / 4);
        float4 v = *reinterpret_cast<const float4*>(xb + (long)r * NVOX + c4 * 4);
        int p = c4 * 4;
        float vv[4] = {v.x, v.y, v.z, v.w};
#pragma unroll
        for (int u = 0; u < 4; u++) {
            int pp = p + u;
            s_xs[r * XROW + (pp / WIN) * PADW + (pp % WIN)] = vv[u];
        }
    }
    __syncthreads();

    // ---- q/k projection, packed f32x2: item = (o-block of 4, position) ----
    if (tid < 2 * TP) {
        int o4  = tid / TP;            // 0 or 1
        int r   = tid % TP;
        int col = (r / WIN) * PADW + (r % WIN);
        u64 aq01 = *(const u64*)&s_bq[o4 * 4];
        u64 aq23 = *(const u64*)&s_bq[o4 * 4 + 2];
        u64 ak01 = *(const u64*)&s_bk[o4 * 4];
        u64 ak23 = *(const u64*)&s_bk[o4 * 4 + 2];
#pragma unroll 8
        for (int c = 0; c < CCH; c++) {
            float xv = s_xs[c * XROW + col];
            u64 xd = dup2(xv);
            ulonglong2 q2 = *(const ulonglong2*)&s_wq[c * CO + o4 * 4];
            ulonglong2 k2 = *(const ulonglong2*)&s_wk[c * CO + o4 * 4];
            aq01 = fma2(q2.x, xd, aq01);
            aq23 = fma2(q2.y, xd, aq23);
            ak01 = fma2(k2.x, xd, ak01);
            ak23 = fma2(k2.y, xd, ak23);
        }
        *(ulonglong2*)&s_qT[r * QKP + o4 * 4] = make_ulonglong2(aq01, aq23);
        *(ulonglong2*)&s_kT[r * QKP + o4 * 4] = make_ulonglong2(ak01, ak23);
    }
    __syncthreads();

    // ---- scores: 8 windows x 13x13, packed dot over 8 channels ----
    for (int m = tid; m < WPB * WIN * WIN; m += NTHREADS) {
        int w  = m / (WIN * WIN);
        int ij = m % (WIN * WIN);
        int ii = ij / WIN, jj = ij % WIN;
        ulonglong2 qa = *(const ulonglong2*)&s_qT[(w * WIN + ii) * QKP];
        ulonglong2 ka = *(const ulonglong2*)&s_kT[(w * WIN + jj) * QKP];
        u64 acc = fma2(qa.x, ka.x, mul2(qa.y, ka.y));
        s_att[w * AWS + ii * ARP + jj] = lo2(acc) + hi2(acc);
        // note: qa.x=(q0,q1) qa.y=(q2,q3); second half:
    }
    // second half of the channel dot (kept separate to limit regs): fold in
    __syncthreads();  // ensure first-half writes land before read-modify-write
    for (int m = tid; m < WPB * WIN * WIN; m += NTHREADS) {
        int w  = m / (WIN * WIN);
        int ij = m % (WIN * WIN);
        int ii = ij / WIN, jj = ij % WIN;
        ulonglong2 qb = *(const ulonglong2*)&s_qT[(w * WIN + ii) * QKP + 4];
        ulonglong2 kb = *(const ulonglong2*)&s_kT[(w * WIN + jj) * QKP + 4];
        u64 acc = fma2(qb.x, kb.x, mul2(qb.y, kb.y));
        s_att[w * AWS + ii * ARP + jj] += lo2(acc) + hi2(acc);
    }
    __syncthreads();

    // ---- softmax over 104 rows of length 13 ----
    if (tid < TP) {
        int w = tid / WIN, ii = tid % WIN;
        float* row = &s_att[w * AWS + ii * ARP];
        float4 ra = *(const float4*)row;
        float4 rb = *(const float4*)(row + 4);
        float4 rc = *(const float4*)(row + 8);
        float  rd = row[12];
        float m0 = fmaxf(fmaxf(fmaxf(ra.x, ra.y), fmaxf(ra.z, ra.w)),
                   fmaxf(fmaxf(fmaxf(rb.x, rb.y), fmaxf(rb.z, rb.w)),
                   fmaxf(fmaxf(fmaxf(rc.x, rc.y), fmaxf(rc.z, rc.w)), rd)));
        ra.x = __expf(ra.x - m0); ra.y = __expf(ra.y - m0);
        ra.z = __expf(ra.z - m0); ra.w = __expf(ra.w - m0);
        rb.x = __expf(rb.x - m0); rb.y = __expf(rb.y - m0);
        rb.z = __expf(rb.z - m0); rb.w = __expf(rb.w - m0);
        rc.x = __expf(rc.x - m0); rc.y = __expf(rc.y - m0);
        rc.z = __expf(rc.z - m0); rc.w = __expf(rc.w - m0);
        rd   = __expf(rd   - m0);
        float sum = ra.x + ra.y + ra.z + ra.w + rb.x + rb.y + rb.z + rb.w
                  + rc.x + rc.y + rc.z + rc.w + rd;
        float inv = __frcp_rn(sum);
        ra.x *= inv; ra.y *= inv; ra.z *= inv; ra.w *= inv;
        rb.x *= inv; rb.y *= inv; rb.z *= inv; rb.w *= inv;
        rc.x *= inv; rc.y *= inv; rc.z *= inv; rc.w *= inv;
        rd   *= inv;
        *(float4*)row       = ra;
        *(float4*)(row + 4) = rb;
        *(float4*)(row + 8) = rc;
        row[12] = rd;
    }
    __syncthreads();

    // ---- fused z = wv@x (2ch x 13pos, packed pairs along j), out = z.att^T + bv ----
    {
        const int ct = tid >> 3;       // 0..31 channel pair
        const int pt = tid & 7;        // 0..7  window
        const int c0 = ct * 2;
        const int col0 = pt * PADW;

        u64 zp0[6], zp1[6];
        float z0s = 0.f, z1s = 0.f;
#pragma unroll
        for (int j = 0; j < 6; j++) { zp0[j] = 0ull; zp1[j] = 0ull; }

#pragma unroll 4
        for (int cc = 0; cc < CCH; cc++) {
            const float* xr = &s_xs[cc * XROW + col0];
            ulonglong2 xA = *(const ulonglong2*)xr;        // (x0,x1),(x2,x3)
            ulonglong2 xB = *(const ulonglong2*)(xr + 4);  // (x4,x5),(x6,x7)
            ulonglong2 xC = *(const ulonglong2*)(xr + 8);  // (x8,x9),(x10,x11)
            float x12 = xr[12];
            float2 wv2 = *(const float2*)&s_wvT[cc * WVP + c0];
            u64 w00 = dup2(wv2.x);
            u64 w11 = dup2(wv2.y);
            zp0[0] = fma2(w00, xA.x, zp0[0]); zp0[1] = fma2(w00, xA.y, zp0[1]);
            zp0[2] = fma2(w00, xB.x, zp0[2]); zp0[3] = fma2(w00, xB.y, zp0[3]);
            zp0[4] = fma2(w00, xC.x, zp0[4]); zp0[5] = fma2(w00, xC.y, zp0[5]);
            z0s = fmaf(wv2.x, x12, z0s);
            zp1[0] = fma2(w11, xA.x, zp1[0]); zp1[1] = fma2(w11, xA.y, zp1[1]);
            zp1[2] = fma2(w11, xB.x, zp1[2]); zp1[3] = fma2(w11, xB.y, zp1[3]);
            zp1[4] = fma2(w11, xC.x, zp1[4]); zp1[5] = fma2(w11, xC.y, zp1[5]);
            z1s = fmaf(wv2.y, x12, z1s);
        }

        const float* ar = &s_att[pt * AWS];
        const float bv0 = s_bv[c0], bv1 = s_bv[c0 + 1];
        float* o0 = ob + (long)c0 * NVOX + pt * WIN;
        float* o1 = o0 + NVOX;
#pragma unroll
        for (int i = 0; i < WIN; i++) {
            const float* ari = ar + i * ARP;
            ulonglong2 aA = *(const ulonglong2*)ari;
            ulonglong2 aB = *(const ulonglong2*)(ari + 4);
            ulonglong2 aC = *(const ulonglong2*)(ari + 8);
            float a12 = ari[12];
            u64 s0 = fma2(zp0[0], aA.x,
                     fma2(zp0[1], aA.y,
                     fma2(zp0[2], aB.x,
                     fma2(zp0[3], aB.y,
                     fma2(zp0[4], aC.x,
                     mul2(zp0[5], aC.y))))));
            u64 s1 = fma2(zp1[0], aA.x,
                     fma2(zp1[1], aA.y,
                     fma2(zp1[2], aB.x,
                     fma2(zp1[3], aB.y,
                     fma2(zp1[4], aC.x,
                     mul2(zp1[5], aC.y))))));
            o0[i] = lo2(s0) + hi2(s0) + fmaf(z0s, a12, bv0);
            o1[i] = lo2(s1) + hi2(s1) + fmaf(z1s, a12, bv1);
        }
    }
}

extern "C" void kernel_launch(void* const* d_in, const int* in_sizes, int n_in,
                              void* d_out, int out_size) {
    const float* x  = (const float*)d_in[0];
    const float* wq = (const float*)d_in[1];
    const float* bq = (const float*)d_in[2];
    const float* wk = (const float*)d_in[3];
    const float* bk = (const float*)d_in[4];
    const float* wv = (const float*)d_in[5];
    const float* bv = (const float*)d_in[6];
    float* out = (float*)d_out;

    const int B = in_sizes[0] / (CCH * NVOX);   // 8

    static bool attr_set = false;
    if (!attr_set) {
        cudaFuncSetAttribute(win_attn_kernel,
                             cudaFuncAttributeMaxDynamicSharedMemorySize, SMEM_BYTES);
        attr_set = true;
    }

    dim3 grid(B * TILES_PER_B);
    win_attn_kernel<<<grid, NTHREADS, SMEM_BYTES>>>(x, wq, bq, wk, bk, wv, bv, out);
}

// round 5
// speedup vs baseline: 1.0356x; 1.0356x over previous
#include <cuda_runtime.h>

#define CCH 64
#define CO 8
#define WIN 13
#define WPB 8
#define TP 104
#define PADW 20          // xs per-window pitch (floats)
#define XROW 160         // WPB*PADW
#define WVP 66           // wvT row pitch
#define QKP 12           // qT/kT row pitch (48B -> conflict-free-ish LDS.128)
#define ARP 20           // att row pitch (floats), aligned float4 rows
#define AWS 260          // att window stride = 13*ARP
#define OBP 108          // staged out buffer pitch (words): all-lane distinct banks
#define NTHREADS 256
#define NVOX 53248
#define TILES_PER_B 512

struct Smem {
    float xs[CCH][XROW];     // 40960 B; aliased as obuf[CCH][OBP] (27648 B) late
    float wvT[CCH][WVP];     // 16896 B
    float wq[CCH][CO];       //  2048 B
    float wk[CCH][CO];       //  2048 B
    float qT[TP][QKP];       //  4992 B
    float kT[TP][QKP];       //  4992 B
    float att[WPB][AWS];     //  8320 B
    float bqs[CO];
    float bks[CO];
    float bvs[CCH];
};                           // ~80.5 KB? -> see static_assert below

__global__ __launch_bounds__(NTHREADS, 3)
void win_attn_kernel(const float* __restrict__ x,
                     const float* __restrict__ wq, const float* __restrict__ bq,
                     const float* __restrict__ wk, const float* __restrict__ bk,
                     const float* __restrict__ wv, const float* __restrict__ bv,
                     float* __restrict__ out) {
    extern __shared__ char smem_raw[];
    Smem& s = *reinterpret_cast<Smem*>(smem_raw);
    float* obuf = &s.xs[0][0];   // aliases xs after it is dead

    const int tid  = threadIdx.x;
    const int b    = blockIdx.x / TILES_PER_B;
    const int tile = blockIdx.x % TILES_PER_B;
    const long n0  = (long)tile * TP;

    const float* xb = x   + (long)b * CCH * NVOX + n0;
    float*       ob = out + (long)b * CCH * NVOX + n0;

    // ---- weights (transposed) + biases ----
    for (int i = tid; i < CO * CCH; i += NTHREADS) {
        int o = i / CCH, c = i % CCH;
        s.wq[c][o] = wq[i];
        s.wk[c][o] = wk[i];
    }
    for (int i = tid; i < CCH * CCH; i += NTHREADS) {
        int c = i / CCH, cc = i % CCH;
        s.wvT[cc][c] = wv[i];
    }
    if (tid < CO)                      s.bqs[tid]       = bq[tid];
    if (tid >= 64 && tid < 64 + CO)    s.bks[tid - 64]  = bk[tid - 64];
    if (tid >= 128 && tid < 128 + CCH) s.bvs[tid - 128] = bv[tid - 128];

    // ---- x tile -> window-padded smem ----
    for (int i = tid; i < CCH * (TP / 4); i += NTHREADS) {
        int r  = i / (TP / 4);
        int c4 = i % (TP / 4);
        float4 v = *reinterpret_cast<const float4*>(xb + (long)r * NVOX + c4 * 4);
        int p = c4 * 4;
        float vv[4] = {v.x, v.y, v.z, v.w};
#pragma unroll
        for (int u = 0; u < 4; u++) {
            int pp = p + u;
            s.xs[r][(pp / WIN) * PADW + (pp % WIN)] = vv[u];
        }
    }
    __syncthreads();

    // ---- q/k projection: (o-block of 4, position), 208 items ----
    if (tid < 2 * TP) {
        int o4  = tid / TP;
        int r   = tid % TP;
        int col = (r / WIN) * PADW + (r % WIN);
        float aq0 = s.bqs[o4 * 4 + 0], aq1 = s.bqs[o4 * 4 + 1];
        float aq2 = s.bqs[o4 * 4 + 2], aq3 = s.bqs[o4 * 4 + 3];
        float ak0 = s.bks[o4 * 4 + 0], ak1 = s.bks[o4 * 4 + 1];
        float ak2 = s.bks[o4 * 4 + 2], ak3 = s.bks[o4 * 4 + 3];
#pragma unroll 8
        for (int c = 0; c < CCH; c++) {
            float  xv = s.xs[c][col];
            float4 q4 = *reinterpret_cast<const float4*>(&s.wq[c][o4 * 4]);
            float4 k4 = *reinterpret_cast<const float4*>(&s.wk[c][o4 * 4]);
            aq0 = fmaf(q4.x, xv, aq0); aq1 = fmaf(q4.y, xv, aq1);
            aq2 = fmaf(q4.z, xv, aq2); aq3 = fmaf(q4.w, xv, aq3);
            ak0 = fmaf(k4.x, xv, ak0); ak1 = fmaf(k4.y, xv, ak1);
            ak2 = fmaf(k4.z, xv, ak2); ak3 = fmaf(k4.w, xv, ak3);
        }
        *reinterpret_cast<float4*>(&s.qT[r][o4 * 4]) = make_float4(aq0, aq1, aq2, aq3);
        *reinterpret_cast<float4*>(&s.kT[r][o4 * 4]) = make_float4(ak0, ak1, ak2, ak3);
    }
    __syncthreads();

    // ---- scores: 8 windows x 13x13 over 8 q/k channels ----
    for (int m = tid; m < WPB * WIN * WIN; m += NTHREADS) {
        int w  = m / (WIN * WIN);
        int ij = m % (WIN * WIN);
        int ii = ij / WIN, jj = ij % WIN;
        float4 qa = *reinterpret_cast<const float4*>(&s.qT[w * WIN + ii][0]);
        float4 qb = *reinterpret_cast<const float4*>(&s.qT[w * WIN + ii][4]);
        float4 ka = *reinterpret_cast<const float4*>(&s.kT[w * WIN + jj][0]);
        float4 kb = *reinterpret_cast<const float4*>(&s.kT[w * WIN + jj][4]);
        float acc = qa.x * ka.x + qa.y * ka.y + qa.z * ka.z + qa.w * ka.w
                  + qb.x * kb.x + qb.y * kb.y + qb.z * kb.z + qb.w * kb.w;
        s.att[w][ii * ARP + jj] = acc;
    }
    __syncthreads();

    // ---- softmax over 104 rows of length 13 (vectorized) ----
    if (tid < TP) {
        int w = tid / WIN, ii = tid % WIN;
        float* row = &s.att[w][ii * ARP];
        float4 ra = *(const float4*)row;
        float4 rb = *(const float4*)(row + 4);
        float4 rc = *(const float4*)(row + 8);
        float  rd = row[12];
        float m0 = fmaxf(fmaxf(fmaxf(ra.x, ra.y), fmaxf(ra.z, ra.w)),
                   fmaxf(fmaxf(fmaxf(rb.x, rb.y), fmaxf(rb.z, rb.w)),
                   fmaxf(fmaxf(fmaxf(rc.x, rc.y), fmaxf(rc.z, rc.w)), rd)));
        ra.x = __expf(ra.x - m0); ra.y = __expf(ra.y - m0);
        ra.z = __expf(ra.z - m0); ra.w = __expf(ra.w - m0);
        rb.x = __expf(rb.x - m0); rb.y = __expf(rb.y - m0);
        rb.z = __expf(rb.z - m0); rb.w = __expf(rb.w - m0);
        rc.x = __expf(rc.x - m0); rc.y = __expf(rc.y - m0);
        rc.z = __expf(rc.z - m0); rc.w = __expf(rc.w - m0);
        rd   = __expf(rd   - m0);
        float sum = ra.x + ra.y + ra.z + ra.w + rb.x + rb.y + rb.z + rb.w
                  + rc.x + rc.y + rc.z + rc.w + rd;
        float inv = __frcp_rn(sum);
        ra.x *= inv; ra.y *= inv; ra.z *= inv; ra.w *= inv;
        rb.x *= inv; rb.y *= inv; rb.z *= inv; rb.w *= inv;
        rc.x *= inv; rc.y *= inv; rc.z *= inv; rc.w *= inv;
        rd   *= inv;
        *(float4*)row       = ra;
        *(float4*)(row + 4) = rb;
        *(float4*)(row + 8) = rc;
        row[12] = rd;
    }
    __syncthreads();

    // ---- z = wv @ x : register tile 2 channels x 13 positions ----
    const int ct = tid >> 3;       // 0..31 channel pair
    const int pt = tid & 7;        // 0..7  window
    const int c0 = ct * 2;
    {
        const int col0 = pt * PADW;
        float z0[WIN], z1[WIN];
#pragma unroll
        for (int j = 0; j < WIN; j++) { z0[j] = 0.f; z1[j] = 0.f; }

#pragma unroll 4
        for (int cc = 0; cc < CCH; cc++) {
            const float* xr = &s.xs[cc][col0];
            float4 xa = *reinterpret_cast<const float4*>(xr);
            float4 xm = *reinterpret_cast<const float4*>(xr + 4);
            float4 xc = *reinterpret_cast<const float4*>(xr + 8);
            float  xd = xr[12];
            float2 wv2 = *reinterpret_cast<const float2*>(&s.wvT[cc][c0]);
            float xv[WIN] = {xa.x, xa.y, xa.z, xa.w,
                             xm.x, xm.y, xm.z, xm.w,
                             xc.x, xc.y, xc.z, xc.w, xd};
#pragma unroll
            for (int j = 0; j < WIN; j++) {
                z0[j] = fmaf(wv2.x, xv[j], z0[j]);
                z1[j] = fmaf(wv2.y, xv[j], z1[j]);
            }
        }

        // xs fully consumed; make alias safe before writing obuf
        __syncthreads();

        // ---- out = z . att^T + bv -> staged in smem (conflict-free) ----
        const float* ar = &s.att[pt][0];
        const float bv0 = s.bvs[c0], bv1 = s.bvs[c0 + 1];
        float* ob0 = obuf + c0 * OBP + pt * WIN;
        float* ob1 = ob0 + OBP;
#pragma unroll
        for (int i = 0; i < WIN; i++) {
            const float* ari = ar + i * ARP;
            float4 aA = *(const float4*)ari;
            float4 aB = *(const float4*)(ari + 4);
            float4 aC = *(const float4*)(ari + 8);
            float  aD = ari[12];
            float s0 = bv0 + z0[0]*aA.x + z0[1]*aA.y + z0[2]*aA.z + z0[3]*aA.w
                           + z0[4]*aB.x + z0[5]*aB.y + z0[6]*aB.z + z0[7]*aB.w
                           + z0[8]*aC.x + z0[9]*aC.y + z0[10]*aC.z + z0[11]*aC.w
                           + z0[12]*aD;
            float s1 = bv1 + z1[0]*aA.x + z1[1]*aA.y + z1[2]*aA.z + z1[3]*aA.w
                           + z1[4]*aB.x + z1[5]*aB.y + z1[6]*aB.z + z1[7]*aB.w
                           + z1[8]*aC.x + z1[9]*aC.y + z1[10]*aC.z + z1[11]*aC.w
                           + z1[12]*aD;
            ob0[i] = s0;
            ob1[i] = s1;
        }
    }
    __syncthreads();

    // ---- coalesced global store: 64 rows x 104 floats as float4 ----
    for (int i = tid; i < CCH * (TP / 4); i += NTHREADS) {
        int r  = i / (TP / 4);
        int c4 = i % (TP / 4);
        float4 v = *reinterpret_cast<const float4*>(obuf + r * OBP + c4 * 4);
        *reinterpret_cast<float4*>(ob + (long)r * NVOX + c4 * 4) = v;
    }
}

extern "C" void kernel_launch(void* const* d_in, const int* in_sizes, int n_in,
                              void* d_out, int out_size) {
    const float* x  = (const float*)d_in[0];
    const float* wq = (const float*)d_in[1];
    const float* bq = (const float*)d_in[2];
    const float* wk = (const float*)d_in[3];
    const float* bk = (const float*)d_in[4];
    const float* wv = (const float*)d_in[5];
    const float* bv = (const float*)d_in[6];
    float* out = (float*)d_out;

    const int B = in_sizes[0] / (CCH * NVOX);   // 8
    const int smem = (int)sizeof(Smem);

    static bool attr_set = false;
    if (!attr_set) {
        cudaFuncSetAttribute(win_attn_kernel,
                             cudaFuncAttributeMaxDynamicSharedMemorySize, smem);
        attr_set = true;
    }

    dim3 grid(B * TILES_PER_B);
    win_attn_kernel<<<grid, NTHREADS, smem>>>(x, wq, bq, wk, bk, wv, bv, out);
}

// round 6
// speedup vs baseline: 1.3346x; 1.2888x over previous
#include <cuda_runtime.h>

#define CCH 64
#define CO 8
#define WIN 13
#define WPB 8
#define TP 104
#define PADW 20          // xs per-window pitch (floats) -> all-8-window distinct bank quads
#define XROW 160         // WPB*PADW
#define WVP 66           // wvT row pitch (2-way store conflict only; 8B-aligned rows)
#define QKP 12           // qT/kT row pitch (48B)
#define ARP 20           // att row pitch
#define AWS 260          // att window stride = 13*ARP
#define OBP 108          // staged out buffer pitch: all-lane distinct banks for scatter
#define NTHREADS 256
#define NVOX 53248
#define TILES_PER_B 512

// byte offsets into dynamic smem (total 76480 -> 3 CTAs/SM)
#define OFF_XS   0          // 64*160*4 = 40960 ; later aliased as obuf[64][108] (27648)
#define OFF_WVT  40960      // 64*66*4  = 16896
#define OFF_WQ   57856      // 64*8*4   = 2048   (dead after q/k proj)
#define OFF_WK   59904      // 2048               (dead after q/k proj)
#define OFF_ATT  57856      // 8*260*4  = 8320   (aliases wq/wk)
#define OFF_QT   66176      // 104*12*4 = 4992
#define OFF_KT   71168      // 4992
#define OFF_BQ   76160
#define OFF_BK   76192
#define OFF_BV   76224      // 256
#define SMEM_BYTES 76480

typedef unsigned long long u64;

__device__ __forceinline__ u64 fma2(u64 a, u64 b, u64 c) {
    u64 d;
    asm("fma.rn.f32x2 %0, %1, %2, %3;" : "=l"(d) : "l"(a), "l"(b), "l"(c));
    return d;
}
__device__ __forceinline__ u64 mul2(u64 a, u64 b) {
    u64 d;
    asm("mul.rn.f32x2 %0, %1, %2;" : "=l"(d) : "l"(a), "l"(b));
    return d;
}
__device__ __forceinline__ u64 dup2(float x) {
    u64 d; unsigned xi = __float_as_uint(x);
    asm("mov.b64 %0, {%1, %1};" : "=l"(d) : "r"(xi));
    return d;
}
__device__ __forceinline__ float lo2(u64 v) { return __uint_as_float((unsigned)v); }
__device__ __forceinline__ float hi2(u64 v) { return __uint_as_float((unsigned)(v >> 32)); }

__global__ __launch_bounds__(NTHREADS, 3)
void win_attn_kernel(const float* __restrict__ x,
                     const float* __restrict__ wq, const float* __restrict__ bq,
                     const float* __restrict__ wk, const float* __restrict__ bk,
                     const float* __restrict__ wv, const float* __restrict__ bv,
                     float* __restrict__ out) {
    extern __shared__ char smem[];
    float* s_xs  = (float*)(smem + OFF_XS);
    float* obuf  = (float*)(smem + OFF_XS);   // aliases xs once dead
    float* s_wvT = (float*)(smem + OFF_WVT);
    float* s_wq  = (float*)(smem + OFF_WQ);
    float* s_wk  = (float*)(smem + OFF_WK);
    float* s_att = (float*)(smem + OFF_ATT);  // aliases wq/wk once dead
    float* s_qT  = (float*)(smem + OFF_QT);
    float* s_kT  = (float*)(smem + OFF_KT);
    float* s_bq  = (float*)(smem + OFF_BQ);
    float* s_bk  = (float*)(smem + OFF_BK);
    float* s_bv  = (float*)(smem + OFF_BV);

    const int tid  = threadIdx.x;
    const int b    = blockIdx.x / TILES_PER_B;
    const int tile = blockIdx.x % TILES_PER_B;
    const long n0  = (long)tile * TP;

    const float* xb = x   + (long)b * CCH * NVOX + n0;
    float*       ob = out + (long)b * CCH * NVOX + n0;

    // ---- weights (transposed) + biases ----
    for (int i = tid; i < CO * CCH; i += NTHREADS) {
        int o = i / CCH, c = i % CCH;
        s_wq[c * CO + o] = wq[i];
        s_wk[c * CO + o] = wk[i];
    }
    for (int i = tid; i < CCH * CCH; i += NTHREADS) {
        int c = i / CCH, cc = i % CCH;
        s_wvT[cc * WVP + c] = wv[i];
    }
    if (tid < CO)                      s_bq[tid]       = bq[tid];
    if (tid >= 64 && tid < 64 + CO)    s_bk[tid - 64]  = bk[tid - 64];
    if (tid >= 128 && tid < 128 + CCH) s_bv[tid - 128] = bv[tid - 128];

    // ---- x tile -> window-padded smem ----
    for (int i = tid; i < CCH * (TP / 4); i += NTHREADS) {
        int r  = i / (TP / 4);
        int c4 = i % (TP / 4);
        float4 v = *reinterpret_cast<const float4*>(xb + (long)r * NVOX + c4 * 4);
        int p = c4 * 4;
        float vv[4] = {v.x, v.y, v.z, v.w};
#pragma unroll
        for (int u = 0; u < 4; u++) {
            int pp = p + u;
            s_xs[r * XROW + (pp / WIN) * PADW + (pp % WIN)] = vv[u];
        }
    }
    __syncthreads();

    // ---- q/k projection: (o4 = tid&1, r = tid>>1) -> conflict-free xs reads ----
    if (tid < 2 * TP) {
        int o4  = tid & 1;
        int r   = tid >> 1;
        int col = (r / WIN) * PADW + (r % WIN);
        u64 aq01 = *(const u64*)&s_bq[o4 * 4];
        u64 aq23 = *(const u64*)&s_bq[o4 * 4 + 2];
        u64 ak01 = *(const u64*)&s_bk[o4 * 4];
        u64 ak23 = *(const u64*)&s_bk[o4 * 4 + 2];
#pragma unroll 8
        for (int c = 0; c < CCH; c++) {
            u64 xd = dup2(s_xs[c * XROW + col]);
            ulonglong2 q2 = *(const ulonglong2*)&s_wq[c * CO + o4 * 4];
            ulonglong2 k2 = *(const ulonglong2*)&s_wk[c * CO + o4 * 4];
            aq01 = fma2(q2.x, xd, aq01);
            aq23 = fma2(q2.y, xd, aq23);
            ak01 = fma2(k2.x, xd, ak01);
            ak23 = fma2(k2.y, xd, ak23);
        }
        *(ulonglong2*)&s_qT[r * QKP + o4 * 4] = make_ulonglong2(aq01, aq23);
        *(ulonglong2*)&s_kT[r * QKP + o4 * 4] = make_ulonglong2(ak01, ak23);
    }
    __syncthreads();

    // ---- scores: single pass, 8 channels packed (att aliases dead wq/wk) ----
    for (int m = tid; m < WPB * WIN * WIN; m += NTHREADS) {
        int w  = m / (WIN * WIN);
        int ij = m % (WIN * WIN);
        int ii = ij / WIN, jj = ij % WIN;
        ulonglong2 qa = *(const ulonglong2*)&s_qT[(w * WIN + ii) * QKP];
        ulonglong2 qb = *(const ulonglong2*)&s_qT[(w * WIN + ii) * QKP + 4];
        ulonglong2 ka = *(const ulonglong2*)&s_kT[(w * WIN + jj) * QKP];
        ulonglong2 kb = *(const ulonglong2*)&s_kT[(w * WIN + jj) * QKP + 4];
        u64 acc = fma2(qa.x, ka.x,
                  fma2(qa.y, ka.y,
                  fma2(qb.x, kb.x,
                  mul2(qb.y, kb.y))));
        s_att[w * AWS + ii * ARP + jj] = lo2(acc) + hi2(acc);
    }
    __syncthreads();

    // ---- softmax over 104 rows of length 13 (vectorized) ----
    if (tid < TP) {
        int w = tid / WIN, ii = tid % WIN;
        float* row = &s_att[w * AWS + ii * ARP];
        float4 ra = *(const float4*)row;
        float4 rb = *(const float4*)(row + 4);
        float4 rc = *(const float4*)(row + 8);
        float  rd = row[12];
        float m0 = fmaxf(fmaxf(fmaxf(ra.x, ra.y), fmaxf(ra.z, ra.w)),
                   fmaxf(fmaxf(fmaxf(rb.x, rb.y), fmaxf(rb.z, rb.w)),
                   fmaxf(fmaxf(fmaxf(rc.x, rc.y), fmaxf(rc.z, rc.w)), rd)));
        ra.x = __expf(ra.x - m0); ra.y = __expf(ra.y - m0);
        ra.z = __expf(ra.z - m0); ra.w = __expf(ra.w - m0);
        rb.x = __expf(rb.x - m0); rb.y = __expf(rb.y - m0);
        rb.z = __expf(rb.z - m0); rb.w = __expf(rb.w - m0);
        rc.x = __expf(rc.x - m0); rc.y = __expf(rc.y - m0);
        rc.z = __expf(rc.z - m0); rc.w = __expf(rc.w - m0);
        rd   = __expf(rd   - m0);
        float sum = ra.x + ra.y + ra.z + ra.w + rb.x + rb.y + rb.z + rb.w
                  + rc.x + rc.y + rc.z + rc.w + rd;
        float inv = __frcp_rn(sum);
        ra.x *= inv; ra.y *= inv; ra.z *= inv; ra.w *= inv;
        rb.x *= inv; rb.y *= inv; rb.z *= inv; rb.w *= inv;
        rc.x *= inv; rc.y *= inv; rc.z *= inv; rc.w *= inv;
        rd   *= inv;
        *(float4*)row       = ra;
        *(float4*)(row + 4) = rb;
        *(float4*)(row + 8) = rc;
        row[12] = rd;
    }
    __syncthreads();

    // ---- z = wv @ x (packed pairs along positions), 2ch x 13pos per thread ----
    {
        const int ct = tid >> 3;       // 0..31 channel pair
        const int pt = tid & 7;        // 0..7  window
        const int c0 = ct * 2;
        const int col0 = pt * PADW;

        u64 zp0[6], zp1[6];
        float z0s = 0.f, z1s = 0.f;
#pragma unroll
        for (int j = 0; j < 6; j++) { zp0[j] = 0ull; zp1[j] = 0ull; }

#pragma unroll 4
        for (int cc = 0; cc < CCH; cc++) {
            const float* xr = &s_xs[cc * XROW + col0];
            ulonglong2 xA = *(const ulonglong2*)xr;
            ulonglong2 xB = *(const ulonglong2*)(xr + 4);
            ulonglong2 xC = *(const ulonglong2*)(xr + 8);
            float x12 = xr[12];
            float2 wv2 = *(const float2*)&s_wvT[cc * WVP + c0];
            u64 w00 = dup2(wv2.x);
            u64 w11 = dup2(wv2.y);
            zp0[0] = fma2(w00, xA.x, zp0[0]); zp0[1] = fma2(w00, xA.y, zp0[1]);
            zp0[2] = fma2(w00, xB.x, zp0[2]); zp0[3] = fma2(w00, xB.y, zp0[3]);
            zp0[4] = fma2(w00, xC.x, zp0[4]); zp0[5] = fma2(w00, xC.y, zp0[5]);
            z0s = fmaf(wv2.x, x12, z0s);
            zp1[0] = fma2(w11, xA.x, zp1[0]); zp1[1] = fma2(w11, xA.y, zp1[1]);
            zp1[2] = fma2(w11, xB.x, zp1[2]); zp1[3] = fma2(w11, xB.y, zp1[3]);
            zp1[4] = fma2(w11, xC.x, zp1[4]); zp1[5] = fma2(w11, xC.y, zp1[5]);
            z1s = fmaf(wv2.y, x12, z1s);
        }

        // xs consumed by every thread; safe to alias as obuf after this barrier
        __syncthreads();

        // ---- out = z . att^T + bv -> staged in obuf (conflict-free scatter) ----
        const float* ar = &s_att[pt * AWS];
        const float bv0 = s_bv[c0], bv1 = s_bv[c0 + 1];
        float* ob0 = obuf + c0 * OBP + pt * WIN;
        float* ob1 = ob0 + OBP;
#pragma unroll
        for (int i = 0; i < WIN; i++) {
            const float* ari = ar + i * ARP;
            ulonglong2 aA = *(const ulonglong2*)ari;
            ulonglong2 aB = *(const ulonglong2*)(ari + 4);
            ulonglong2 aC = *(const ulonglong2*)(ari + 8);
            float a12 = ari[12];
            u64 s0 = fma2(zp0[0], aA.x,
                     fma2(zp0[1], aA.y,
                     fma2(zp0[2], aB.x,
                     fma2(zp0[3], aB.y,
                     fma2(zp0[4], aC.x,
                     mul2(zp0[5], aC.y))))));
            u64 s1 = fma2(zp1[0], aA.x,
                     fma2(zp1[1], aA.y,
                     fma2(zp1[2], aB.x,
                     fma2(zp1[3], aB.y,
                     fma2(zp1[4], aC.x,
                     mul2(zp1[5], aC.y))))));
            ob0[i] = lo2(s0) + hi2(s0) + fmaf(z0s, a12, bv0);
            ob1[i] = lo2(s1) + hi2(s1) + fmaf(z1s, a12, bv1);
        }
    }
    __syncthreads();

    // ---- coalesced global store: 64 rows x 104 floats as float4 ----
    for (int i = tid; i < CCH * (TP / 4); i += NTHREADS) {
        int r  = i / (TP / 4);
        int c4 = i % (TP / 4);
        float4 v = *reinterpret_cast<const float4*>(obuf + r * OBP + c4 * 4);
        *reinterpret_cast<float4*>(ob + (long)r * NVOX + c4 * 4) = v;
    }
}

extern "C" void kernel_launch(void* const* d_in, const int* in_sizes, int n_in,
                              void* d_out, int out_size) {
    const float* x  = (const float*)d_in[0];
    const float* wq = (const float*)d_in[1];
    const float* bq = (const float*)d_in[2];
    const float* wk = (const float*)d_in[3];
    const float* bk = (const float*)d_in[4];
    const float* wv = (const float*)d_in[5];
    const float* bv = (const float*)d_in[6];
    float* out = (float*)d_out;

    const int B = in_sizes[0] / (CCH * NVOX);   // 8

    static bool attr_set = false;
    if (!attr_set) {
        cudaFuncSetAttribute(win_attn_kernel,
                             cudaFuncAttributeMaxDynamicSharedMemorySize, SMEM_BYTES);
        attr_set = true;
    }

    dim3 grid(B * TILES_PER_B);
    win_attn_kernel<<<grid, NTHREADS, SMEM_BYTES>>>(x, wq, bq, wk, bk, wv, bv, out);
}